// round 11
// baseline (speedup 1.0000x reference)
#include <cuda_runtime.h>
#include <cstdint>

// Problem sizes (fixed by dataset)
#define TOK    8192      // B*S
#define DDIM   1024
#define NPOOL  64
#define RDIM   128

// h partials: [4 n-quarters][TOK][RDIM]  (16 MB static device scratch)
__device__ float g_h[4u * TOK * RDIM];

// ---------------- helpers ----------------
__device__ __forceinline__ uint32_t smem_u32(const void* p) {
    uint32_t a;
    asm("{ .reg .u64 t; cvta.to.shared.u64 t, %1; cvt.u32.u64 %0, t; }" : "=r"(a) : "l"(p));
    return a;
}
__device__ __forceinline__ uint32_t f2tf32(float f) {
    uint32_t u;
    asm("cvt.rna.tf32.f32 %0, %1;" : "=r"(u) : "f"(f));
    return u;
}
__device__ __forceinline__ void cp_async16(uint32_t smem_dst, const void* gptr) {
    asm volatile("cp.async.cg.shared.global [%0], [%1], 16;" :: "r"(smem_dst), "l"(gptr) : "memory");
}
#define MBARRIER_INIT(addr, cnt) \
    asm volatile("mbarrier.init.shared.b64 [%0], %1;" :: "r"((uint32_t)(addr)), "r"((uint32_t)(cnt)) : "memory")
#define MBARRIER_ARRIVE(addr) \
    asm volatile("mbarrier.arrive.shared.b64 _, [%0];" :: "r"((uint32_t)(addr)) : "memory")
// .noinc is load-bearing: default form is count-neutral; .noinc contributes to expected count.
#define CP_MBAR_ARRIVE(addr) \
    asm volatile("cp.async.mbarrier.arrive.noinc.shared.b64 [%0];" :: "r"((uint32_t)(addr)) : "memory")

#define MBARRIER_WAIT_PARITY(addr, par) do { \
    uint32_t _m = (uint32_t)(addr), _p = (uint32_t)(par), _d; \
    asm volatile("{ .reg .pred p; mbarrier.try_wait.parity.acquire.cta.shared::cta.b64 p, [%1], %2; selp.b32 %0,1,0,p; }" \
        : "=r"(_d) : "r"(_m), "r"(_p) : "memory"); \
    if (!_d) { \
        asm volatile("{ .reg .pred P1; WL_%=: mbarrier.try_wait.parity.acquire.cta.shared::cta.b64 P1, [%0], %1, 0x989680; @P1 bra.uni WD_%=; bra.uni WL_%=; WD_%=: }" \
            :: "r"(_m), "r"(_p) : "memory"); \
    } } while (0)

__device__ __forceinline__ void mma_tf32(float* c, const uint32_t* a, uint32_t b0, uint32_t b1) {
    asm volatile(
        "mma.sync.aligned.m16n8k8.row.col.f32.tf32.tf32.f32 "
        "{%0,%1,%2,%3}, {%4,%5,%6,%7}, {%8,%9}, {%0,%1,%2,%3};"
        : "+f"(c[0]), "+f"(c[1]), "+f"(c[2]), "+f"(c[3])
        : "r"(a[0]), "r"(a[1]), "r"(a[2]), "r"(a[3]), "r"(b0), "r"(b1));
}

// Swizzled SMEM indexing (float units), conflict-free for all used patterns.
// A: [m][k], rows x 32 ;  B: [k][n], 32 x NC
#define AIDX(m, k) ((m) * 32 + ((k) ^ (((m) & 7) << 2)))
template<int NC>
__device__ __forceinline__ int bidx(int k, int n) { return k * NC + ((n) ^ (((k) & 3) << 3)); }

// SMEM: [0..1023] barriers (256 floats); then NST stages x 12288 floats (48KB):
//   stage1: A 8192 floats (256x32), B 4096 floats (32x128)
//   stage2: A 4096 floats (128x32), B 8192 floats (32x256)
#define NST 4
#define STAGE_FLTS 12288
#define SM_BASE(s) (256 + (s) * STAGE_FLTS)
#define SMEM_BYTES ((256 + NST * STAGE_FLTS) * 4)
// barrier byte offsets from smem base: full[s] = s*8 ; empty[s] = 64 + s*8

// ---------------- consumer compute core: 64x64 warp tile ----------------
struct Frag { float c[4][8][4]; };   // 128 accum regs

template<int NC>
__device__ __forceinline__ void compute64(const uint32_t* __restrict__ As,
                                          const uint32_t* __restrict__ Bs,
                                          int rA, int ncol, int cA, int nB, int kB, Frag& F) {
    #pragma unroll
    for (int ks = 0; ks < 4; ++ks) {
        int k0 = ks * 8;
        uint32_t a[4][4];
        #pragma unroll
        for (int mt = 0; mt < 4; ++mt) {
            int m = rA + mt * 16;
            a[mt][0] = As[AIDX(m,     k0 + cA)];
            a[mt][1] = As[AIDX(m + 8, k0 + cA)];
            a[mt][2] = As[AIDX(m,     k0 + 4 + cA)];
            a[mt][3] = As[AIDX(m + 8, k0 + 4 + cA)];
        }
        #pragma unroll
        for (int np = 0; np < 4; ++np) {     // nt pairs: keeps live b-regs at 4
            uint32_t b[2][2];
            #pragma unroll
            for (int j = 0; j < 2; ++j) {
                int n = ncol + (np * 2 + j) * 8 + nB;
                b[j][0] = Bs[bidx<NC>(k0 + kB,     n)];
                b[j][1] = Bs[bidx<NC>(k0 + 4 + kB, n)];
            }
            #pragma unroll
            for (int j = 0; j < 2; ++j)
                #pragma unroll
                for (int mt = 0; mt < 4; ++mt)
                    mma_tf32(F.c[mt][np * 2 + j], a[mt], b[j][0], b[j][1]);
        }
    }
}

__device__ __forceinline__ void zero_frag(Frag& F) {
    #pragma unroll
    for (int mt = 0; mt < 4; ++mt)
        #pragma unroll
        for (int nt = 0; nt < 8; ++nt)
            #pragma unroll
            for (int q = 0; q < 4; ++q) F.c[mt][nt][q] = 0.f;
}

// ==================== Stage 1 ====================
// grid (32 token-tiles of 256, 4 n-quarters). C[256 tok,128 r] over K = 16 n * 1024 d.
// chunk c: d-block = c>>4 (outer), n = n0 + (c&15) (inner) -> x cached in producer regs
__global__ __launch_bounds__(384, 1)
void kc_stage1(const float* __restrict__ x, const float* __restrict__ fw,
               const float* __restrict__ FK) {
    extern __shared__ uint32_t smem[];
    uint32_t sb = smem_u32(smem);
    int tid = threadIdx.x, wid = tid >> 5, lane = tid & 31;
    int tok0 = blockIdx.x * 256;
    int n0 = blockIdx.y * 16;
    const int CHUNKS = 32 * 16;  // 512

    if (tid == 0) {
        #pragma unroll
        for (int s = 0; s < NST; ++s) {
            MBARRIER_INIT(sb + s * 8, 256);       // full: 128 STS-arrives + 128 cp-noinc
            MBARRIER_INIT(sb + 64 + s * 8, 256);  // empty: 256 consumer threads
        }
    }
    __syncthreads();

    if (wid >= 8) {
        // ---------------- producer (4 warps) ----------------
        int pt = tid - 256;          // 0..127
        int rbase = pt >> 3;         // 0..15 -> rows rbase + 16*p, p=0..15
        int g4 = (pt & 7) * 4;
        float4 xc[16];               // x cache: 16 rows x 4 k
        int st = 0, ph = 1;
        for (int c = 0; c < CHUNKS; ++c) {
            int d0 = (c >> 4) * 32;
            int n = n0 + (c & 15);
            if ((c & 15) == 0) {
                #pragma unroll
                for (int p = 0; p < 16; ++p)
                    xc[p] = *(const float4*)&x[(size_t)(tok0 + rbase + 16 * p) * DDIM + d0 + g4];
            }
            MBARRIER_WAIT_PARITY(sb + 64 + st * 8, ph);
            uint32_t* A = smem + SM_BASE(st);
            #pragma unroll
            for (int p = 0; p < 16; ++p) {
                int m = rbase + 16 * p;
                float w = fw[(tok0 + m) * NPOOL + n];
                uint4 t4;
                t4.x = f2tf32(xc[p].x * w); t4.y = f2tf32(xc[p].y * w);
                t4.z = f2tf32(xc[p].z * w); t4.w = f2tf32(xc[p].w * w);
                *(uint4*)&A[AIDX(m, g4)] = t4;
            }
            MBARRIER_ARRIVE(sb + st * 8);
            uint32_t bb = sb + 4u * (SM_BASE(st) + 8192);
            #pragma unroll
            for (int it = 0; it < 8; ++it) {
                int idx = pt + it * 128;
                int k = idx >> 5, q = idx & 31;
                cp_async16(bb + 4u * bidx<128>(k, q * 4),
                           &FK[((size_t)n * DDIM + d0 + k) * RDIM + q * 4]);
            }
            CP_MBAR_ARRIVE(sb + st * 8);
            if (++st == NST) { st = 0; ph ^= 1; }
        }
        return;
    }

    // ---------------- consumers (8 warps, 64x64 tiles: 4 row-bands x 2 col-bands) ----------------
    int mb = wid & 3, nb = wid >> 2;
    int rA = mb * 64 + (lane >> 2);
    int ncol = nb * 64;
    int cA = lane & 3, nB = lane >> 2, kB = lane & 3;
    Frag F;
    zero_frag(F);
    {
        int st = 0, ph = 0;
        for (int c = 0; c < CHUNKS; ++c) {
            MBARRIER_WAIT_PARITY(sb + st * 8, ph);
            compute64<128>(smem + SM_BASE(st), smem + SM_BASE(st) + 8192, rA, ncol, cA, nB, kB, F);
            MBARRIER_ARRIVE(sb + 64 + st * 8);
            if (++st == NST) { st = 0; ph ^= 1; }
        }
    }
    // epilogue: write h partial
    {
        size_t hb = (size_t)blockIdx.y * TOK;
        #pragma unroll
        for (int mt = 0; mt < 4; ++mt) {
            int row = tok0 + mb * 64 + mt * 16 + (lane >> 2);
            #pragma unroll
            for (int nt = 0; nt < 8; ++nt) {
                int col = ncol + nt * 8 + (lane & 3) * 2;
                *(float2*)&g_h[(hb + row) * RDIM + col]     = make_float2(F.c[mt][nt][0], F.c[mt][nt][1]);
                *(float2*)&g_h[(hb + row + 8) * RDIM + col] = make_float2(F.c[mt][nt][2], F.c[mt][nt][3]);
            }
        }
    }
}

// ==================== Stage 2 ====================
// grid (64 token-tiles of 128, 4 d-tiles of 256). out over K = 64 n * 128 r.
// chunk c: r-block = c>>6 (outer), n = c&63 (inner) -> summed-h cached in producer regs
__global__ __launch_bounds__(384, 1)
void kc_stage2(const float* __restrict__ rw, const float* __restrict__ RK,
               float* __restrict__ out) {
    extern __shared__ uint32_t smem[];
    uint32_t sb = smem_u32(smem);
    int tid = threadIdx.x, wid = tid >> 5, lane = tid & 31;
    int tok0 = blockIdx.x * 128;
    int dt0 = blockIdx.y * 256;
    const int CHUNKS = 4 * 64;  // 256

    if (tid == 0) {
        #pragma unroll
        for (int s = 0; s < NST; ++s) {
            MBARRIER_INIT(sb + s * 8, 256);
            MBARRIER_INIT(sb + 64 + s * 8, 256);
        }
    }
    __syncthreads();

    if (wid >= 8) {
        // ---------------- producer ----------------
        int pt = tid - 256;
        int rbase = pt >> 3;         // rows rbase + 16*p, p=0..7
        int g4 = (pt & 7) * 4;
        float4 hc[8];                // (h0+h1+h2+h3) cache
        int st = 0, ph = 1;
        for (int c = 0; c < CHUNKS; ++c) {
            int r0 = (c >> 6) * 32;
            int n = c & 63;
            if ((c & 63) == 0) {
                #pragma unroll
                for (int p = 0; p < 8; ++p) {
                    size_t ho = (size_t)(tok0 + rbase + 16 * p) * RDIM + r0 + g4;
                    float4 v0 = *(const float4*)&g_h[ho];
                    float4 v1 = *(const float4*)&g_h[1u * TOK * RDIM + ho];
                    float4 v2 = *(const float4*)&g_h[2u * TOK * RDIM + ho];
                    float4 v3 = *(const float4*)&g_h[3u * TOK * RDIM + ho];
                    hc[p] = make_float4((v0.x + v1.x) + (v2.x + v3.x),
                                        (v0.y + v1.y) + (v2.y + v3.y),
                                        (v0.z + v1.z) + (v2.z + v3.z),
                                        (v0.w + v1.w) + (v2.w + v3.w));
                }
            }
            MBARRIER_WAIT_PARITY(sb + 64 + st * 8, ph);
            uint32_t* A = smem + SM_BASE(st);
            #pragma unroll
            for (int p = 0; p < 8; ++p) {
                int m = rbase + 16 * p;
                float w = rw[(tok0 + m) * NPOOL + n];
                uint4 t4;
                t4.x = f2tf32(hc[p].x * w); t4.y = f2tf32(hc[p].y * w);
                t4.z = f2tf32(hc[p].z * w); t4.w = f2tf32(hc[p].w * w);
                *(uint4*)&A[AIDX(m, g4)] = t4;
            }
            MBARRIER_ARRIVE(sb + st * 8);
            uint32_t bb = sb + 4u * (SM_BASE(st) + 4096);
            #pragma unroll
            for (int it = 0; it < 16; ++it) {
                int idx = pt + it * 128;
                int k = idx >> 6, q = idx & 63;
                cp_async16(bb + 4u * bidx<256>(k, q * 4),
                           &RK[((size_t)n * RDIM + r0 + k) * DDIM + dt0 + q * 4]);
            }
            CP_MBAR_ARRIVE(sb + st * 8);
            if (++st == NST) { st = 0; ph ^= 1; }
        }
        return;
    }

    // ---------------- consumers (8 warps, 64x64 tiles: 2 row-bands x 4 col-bands) ----------------
    int mb = wid & 1, nb = wid >> 1;
    int rA = mb * 64 + (lane >> 2);
    int ncol = nb * 64;
    int cA = lane & 3, nB = lane >> 2, kB = lane & 3;
    Frag F;
    zero_frag(F);
    {
        int st = 0, ph = 0;
        for (int c = 0; c < CHUNKS; ++c) {
            MBARRIER_WAIT_PARITY(sb + st * 8, ph);
            compute64<256>(smem + SM_BASE(st), smem + SM_BASE(st) + 4096, rA, ncol, cA, nB, kB, F);
            MBARRIER_ARRIVE(sb + 64 + st * 8);
            if (++st == NST) { st = 0; ph ^= 1; }
        }
    }
    // epilogue: write out
    {
        #pragma unroll
        for (int mt = 0; mt < 4; ++mt) {
            int row = tok0 + mb * 64 + mt * 16 + (lane >> 2);
            #pragma unroll
            for (int nt = 0; nt < 8; ++nt) {
                int col = dt0 + ncol + nt * 8 + (lane & 3) * 2;
                *(float2*)&out[(size_t)row * DDIM + col]       = make_float2(F.c[mt][nt][0], F.c[mt][nt][1]);
                *(float2*)&out[(size_t)(row + 8) * DDIM + col] = make_float2(F.c[mt][nt][2], F.c[mt][nt][3]);
            }
        }
    }
}

// ==================== launch ====================
extern "C" void kernel_launch(void* const* d_in, const int* in_sizes, int n_in,
                              void* d_out, int out_size) {
    const float* x  = (const float*)d_in[0];
    const float* fw = (const float*)d_in[1];
    const float* rw = (const float*)d_in[2];
    const float* FK = (const float*)d_in[3];
    const float* RK = (const float*)d_in[4];
    float* out = (float*)d_out;

    cudaFuncSetAttribute(kc_stage1, cudaFuncAttributeMaxDynamicSharedMemorySize, SMEM_BYTES);
    cudaFuncSetAttribute(kc_stage2, cudaFuncAttributeMaxDynamicSharedMemorySize, SMEM_BYTES);

    kc_stage1<<<dim3(32, 4), 384, SMEM_BYTES>>>(x, fw, FK);
    kc_stage2<<<dim3(64, 4), 384, SMEM_BYTES>>>(rw, RK, out);
}